// round 15
// baseline (speedup 1.0000x reference)
#include <cuda_runtime.h>
#include <cuda_fp16.h>
#include <cstdint>

// Problem constants (fixed by the reference)
#define M_ITEMS 100000
#define N_USERS 50000
#define DIM     64
#define NB      (M_ITEMS * DIM)   // 6,400,000 floats
#define NU      (N_USERS * DIM)   // 3,200,000 floats
#define E_II_MAX 3200000
#define E_UI_MAX 1600000

#define SCAN_CHUNK  1024
#define SCAN_BLOCKS ((M_ITEMS + SCAN_CHUNK - 1) / SCAN_CHUNK)  // 98

// Static device scratch (no allocations allowed).
__device__ uint2 g_h0[NB / 4];          // half(emb)
__device__ uint2 g_h1[NB / 4];          // e1
__device__ uint2 g_h2[NB / 4];          // e2
__device__ float g_sum[NB];             // all_items*4 (written by fused spmm L2)
__device__ float g_users[NU];           // all_users (only batch rows zeroed/used)
__device__ int   g_cnt[M_ITEMS];        // per-row counts (re-zeroed by k_scan)
__device__ int   g_rowptr[M_ITEMS + 1]; // CSR row pointers
__device__ int   g_pos[M_ITEMS];        // scatter fill cursors
__device__ int2  g_epack[E_II_MAX];     // CSR: (dst*16, val-bits) per edge
__device__ int   g_sync[SCAN_BLOCKS];   // lookback: aggregate+1, 0 = not ready
__device__ unsigned char g_uflag[N_USERS]; // batch-user flags (set-only, idempotent)
__device__ int   g_uecnt;               // compacted ui-edge count (reset in k_pre)
__device__ int4  g_ue4[E_UI_MAX];       // compacted ui edges: (u*16, i*16, valbits, -)

// Vector reduction-add to global (sm_90+)
__device__ __forceinline__ void red_add_f4(float4* addr, float4 v) {
    asm volatile("red.global.add.v4.f32 [%0], {%1, %2, %3, %4};"
                 :: "l"(addr), "f"(v.x), "f"(v.y), "f"(v.z), "f"(v.w)
                 : "memory");
}

// Streaming (evict-first) accesses for once-touched data.
__device__ __forceinline__ int2 ldcs_int2(const int2* p) {
    int2 r;
    asm volatile("ld.global.cs.v2.b32 {%0, %1}, [%2];"
                 : "=r"(r.x), "=r"(r.y) : "l"(p));
    return r;
}
__device__ __forceinline__ void stcs_uint2(uint2* p, uint2 v) {
    asm volatile("st.global.cs.v2.b32 [%0], {%1, %2};"
                 :: "l"(p), "r"(v.x), "r"(v.y));
}

__device__ __forceinline__ int block_reduce_sum(int v, int* sw) {
    #pragma unroll
    for (int o = 16; o; o >>= 1) v += __shfl_xor_sync(0xFFFFFFFFu, v, o);
    int w = threadIdx.x >> 5;
    if ((threadIdx.x & 31) == 0) sw[w] = v;
    __syncthreads();
    if (threadIdx.x < 8) {
        v = sw[threadIdx.x];
        #pragma unroll
        for (int o = 4; o; o >>= 1) v += __shfl_xor_sync(0xFFu, v, o);
        if (threadIdx.x == 0) sw[0] = v;
    }
    __syncthreads();
    int r = sw[0];
    __syncthreads();
    return r;
}

// Fused: g_h0 = half(emb), histogram of ii_src, batch-user flag + row zeroing,
// counter resets.
__global__ void k_pre(const float* __restrict__ emb, const int* __restrict__ src,
                      int ne, const int* __restrict__ users, int nusers) {
    int i = blockIdx.x * blockDim.x + threadIdx.x;
    if (i < NB / 8) {
        const float4* e4 = (const float4*)emb;
        float4 a = __ldg(e4 + 2 * i);
        float4 b = __ldg(e4 + 2 * i + 1);
        __half2 h0 = __floats2half2_rn(a.x, a.y);
        __half2 h1 = __floats2half2_rn(a.z, a.w);
        __half2 h2 = __floats2half2_rn(b.x, b.y);
        __half2 h3 = __floats2half2_rn(b.z, b.w);
        uint4 hp;
        hp.x = *reinterpret_cast<unsigned int*>(&h0);
        hp.y = *reinterpret_cast<unsigned int*>(&h1);
        hp.z = *reinterpret_cast<unsigned int*>(&h2);
        hp.w = *reinterpret_cast<unsigned int*>(&h3);
        ((uint4*)g_h0)[i] = hp;
    }
    if (i < nusers * 16) {
        int b = i >> 4, l = i & 15;
        int u = __ldg(users + b);
        if (l == 0) g_uflag[u] = 1;
        ((float4*)g_users)[(long)u * 16 + l] = make_float4(0.f, 0.f, 0.f, 0.f);
    }
    if (i < SCAN_BLOCKS) g_sync[i] = 0;
    if (i == 0) g_uecnt = 0;
    if (i < ne) atomicAdd(&g_cnt[__ldg(src + i)], 1);
}

// Single-kernel exclusive scan with decoupled lookback (98 co-resident blocks).
__global__ void k_scan() {
    __shared__ int s[256];
    __shared__ int sw[8];
    int tid = threadIdx.x, b = blockIdx.x;

    int idx0 = b * SCAN_CHUNK + tid * 4;
    int c[4];
    #pragma unroll
    for (int i = 0; i < 4; i++) {
        int idx = idx0 + i;
        c[i] = (idx < M_ITEMS) ? g_cnt[idx] : 0;
    }
    int t4 = c[0] + c[1] + c[2] + c[3];

    int agg = block_reduce_sum(t4, sw);
    if (tid == 0) atomicExch(&g_sync[b], agg + 1);

    int pre = 0;
    if (tid < b) {
        int v;
        do { v = atomicAdd(&g_sync[tid], 0); } while (v == 0);
        pre = v - 1;
    }
    int blockOff = block_reduce_sum(pre, sw);

    s[tid] = t4;
    __syncthreads();
    for (int off = 1; off < 256; off <<= 1) {
        int t = (tid >= off) ? s[tid - off] : 0;
        __syncthreads();
        s[tid] += t;
        __syncthreads();
    }
    int run = blockOff + ((tid == 0) ? 0 : s[tid - 1]);
    #pragma unroll
    for (int i = 0; i < 4; i++) {
        int idx = idx0 + i;
        if (idx < M_ITEMS) {
            g_rowptr[idx] = run;
            g_pos[idx]    = run;
            g_cnt[idx]    = 0;
            run += c[i];
        }
    }
    if (b == SCAN_BLOCKS - 1 && tid == 255) g_rowptr[M_ITEMS] = run;
}

// scatter edges into CSR order, 8 independent edges per thread (MLP=8).
// Stores dst PREMULTIPLIED by 16 (uint2-row offset).
__global__ void k_scatter(const int* __restrict__ src, const int* __restrict__ dst,
                          const float* __restrict__ val, int n) {
    int i = blockIdx.x * blockDim.x + threadIdx.x;
    int Q = (n + 7) >> 3;
    if (i >= Q) return;
    int e[8]; int s[8]; int2 dv[8]; int p[8];
    #pragma unroll
    for (int k = 0; k < 8; k++) {
        e[k] = i + k * Q;
        if (e[k] < n) {
            s[k]  = __ldg(src + e[k]);
            dv[k] = make_int2(__ldg(dst + e[k]) << 4, __float_as_int(__ldg(val + e[k])));
        }
    }
    #pragma unroll
    for (int k = 0; k < 8; k++)
        if (e[k] < n) p[k] = atomicAdd(&g_pos[s[k]], 1);
    #pragma unroll
    for (int k = 0; k < 8; k++)
        if (e[k] < n) g_epack[p[k]] = dv[k];
}

// Pull SpMM (proven shape): one warp per row, TWO edges per iteration
// (16 lanes/edge), 8B/lane. Edge records .cs, gathers .nc.
// Layer 0/1 (emb==nullptr): store att*acc as half to yh.
// Layer 2  (emb!=nullptr): FUSED k_post — writer lanes read emb/h1/h2 at their
// own row offset, add e3 in fp32, write g_sum directly. No half store.
__global__ void k_spmm_pull(const uint2* __restrict__ x, uint2* __restrict__ yh,
                            const float* __restrict__ att, int layer,
                            const float* __restrict__ emb) {
    int row  = blockIdx.x * (blockDim.x >> 5) + (threadIdx.x >> 5);
    int lane = threadIdx.x & 31;
    if (row >= M_ITEMS) return;
    int lane16 = lane & 15;
    int sub    = lane >> 4;

    int beg = g_rowptr[row];
    int end = g_rowptr[row + 1];

    float4 acc = make_float4(0.0f, 0.0f, 0.0f, 0.0f);

    if ((end - beg) & 1) {                    // peel odd edge
        int2 ed = ldcs_int2(&g_epack[beg]);
        float v = (sub == 0) ? __int_as_float(ed.y) : 0.0f;
        uint2 raw = __ldg(x + (unsigned)(ed.x | lane16));
        float2 f0 = __half22float2(*reinterpret_cast<__half2*>(&raw.x));
        float2 f1 = __half22float2(*reinterpret_cast<__half2*>(&raw.y));
        acc.x = fmaf(v, f0.x, acc.x);
        acc.y = fmaf(v, f0.y, acc.y);
        acc.z = fmaf(v, f1.x, acc.z);
        acc.w = fmaf(v, f1.y, acc.w);
        beg++;
    }
    #pragma unroll 4
    for (int e = beg; e < end; e += 2) {
        int2  ed = ldcs_int2(&g_epack[e + sub]);
        float v  = __int_as_float(ed.y);
        uint2 raw = __ldg(x + (unsigned)(ed.x | lane16));
        float2 f0 = __half22float2(*reinterpret_cast<__half2*>(&raw.x));
        float2 f1 = __half22float2(*reinterpret_cast<__half2*>(&raw.y));
        acc.x = fmaf(v, f0.x, acc.x);
        acc.y = fmaf(v, f0.y, acc.y);
        acc.z = fmaf(v, f1.x, acc.z);
        acc.w = fmaf(v, f1.y, acc.w);
    }
    acc.x += __shfl_xor_sync(0xFFFFFFFFu, acc.x, 16);
    acc.y += __shfl_xor_sync(0xFFFFFFFFu, acc.y, 16);
    acc.z += __shfl_xor_sync(0xFFFFFFFFu, acc.z, 16);
    acc.w += __shfl_xor_sync(0xFFFFFFFFu, acc.w, 16);

    if (sub == 0) {
        float a = __ldg(att + layer);
        unsigned o = (unsigned)row * 16u + lane16;
        if (emb == nullptr) {
            __half2 p0 = __floats2half2_rn(acc.x * a, acc.y * a);
            __half2 p1 = __floats2half2_rn(acc.z * a, acc.w * a);
            uint2 hp;
            hp.x = *reinterpret_cast<unsigned int*>(&p0);
            hp.y = *reinterpret_cast<unsigned int*>(&p1);
            stcs_uint2(yh + o, hp);
        } else {
            // fused k_post: g_sum = emb + e1 + e2 + e3(fp32)
            float4 s = __ldg((const float4*)emb + o);
            uint2 r1 = __ldg(g_h1 + o);
            uint2 r2 = __ldg(g_h2 + o);
            float2 a0 = __half22float2(*reinterpret_cast<__half2*>(&r1.x));
            float2 a1 = __half22float2(*reinterpret_cast<__half2*>(&r1.y));
            float2 b0 = __half22float2(*reinterpret_cast<__half2*>(&r2.x));
            float2 b1 = __half22float2(*reinterpret_cast<__half2*>(&r2.y));
            s.x += a0.x + b0.x + acc.x * a;
            s.y += a0.y + b0.y + acc.y * a;
            s.z += a1.x + b1.x + acc.z * a;
            s.w += a1.y + b1.y + acc.w * a;
            ((float4*)g_sum)[o] = s;
        }
    }
}

// ui phase A: compact edges whose user is in the batch, 4 edges/thread (MLP=4
// on the src-load -> uflag-gather chain).
__global__ void k_ui_filter(const int* __restrict__ src, const int* __restrict__ dst,
                            const float* __restrict__ val, int n) {
    int i = blockIdx.x * blockDim.x + threadIdx.x;
    int Q = (n + 3) >> 2;
    if (i >= Q) return;
    int e[4]; int s[4]; unsigned char f[4];
    #pragma unroll
    for (int k = 0; k < 4; k++) {
        e[k] = i + k * Q;
        s[k] = (e[k] < n) ? __ldg(src + e[k]) : 0;
    }
    #pragma unroll
    for (int k = 0; k < 4; k++)
        f[k] = (e[k] < n) ? g_uflag[s[k]] : 0;
    #pragma unroll
    for (int k = 0; k < 4; k++) {
        if (f[k]) {
            int p = atomicAdd(&g_uecnt, 1);
            g_ue4[p] = make_int4(s[k] << 4, __ldg(dst + e[k]) << 4,
                                 __float_as_int(__ldg(val + e[k])), 0);
        }
    }
}

// ui phase B: grid-stride over the compacted list, 2 edges/warp, 16 lanes/edge.
__global__ void k_ui_gather() {
    int K = g_uecnt;
    int warps = (gridDim.x * blockDim.x) >> 5;
    int w     = (blockIdx.x * blockDim.x + threadIdx.x) >> 5;
    int lane  = threadIdx.x & 31;
    int lane16 = lane & 15;
    int sub    = lane >> 4;

    for (int i = w * 2 + sub; i < K; i += warps * 2) {
        int4 t = __ldg(&g_ue4[i]);
        float v = __int_as_float(t.z) * 0.25f;
        float4 xv = __ldg((const float4*)g_sum + (unsigned)(t.y | lane16));
        float4 r  = make_float4(xv.x * v, xv.y * v, xv.z * v, xv.w * v);
        red_add_f4((float4*)g_users + (unsigned)(t.x | lane16), r);
    }
}

// gamma[b] = dot(g_users[u], 0.25 * g_sum[i]); one warp per pair
__global__ void k_dot(const int* __restrict__ users, const int* __restrict__ items,
                      float* __restrict__ out, int nb) {
    int w    = (blockIdx.x * blockDim.x + threadIdx.x) >> 5;
    int lane = threadIdx.x & 31;
    if (w >= nb) return;

    int u = __ldg(users + w);
    int i = __ldg(items + w);

    float2 a = __ldg((const float2*)g_users + (long)u * 32 + lane);
    float2 b = __ldg((const float2*)g_sum   + (long)i * 32 + lane);
    float p = a.x * b.x + a.y * b.y;

    #pragma unroll
    for (int o = 16; o; o >>= 1) p += __shfl_xor_sync(0xFFFFFFFFu, p, o);

    if (lane == 0) out[w] = 0.25f * p;
}

extern "C" void kernel_launch(void* const* d_in, const int* in_sizes, int n_in,
                              void* d_out, int out_size) {
    const int*   users  = (const int*)d_in[0];
    const int*   items  = (const int*)d_in[1];
    const int*   ii_src = (const int*)d_in[2];
    const int*   ii_dst = (const int*)d_in[3];
    const float* ii_val = (const float*)d_in[4];
    const int*   ui_src = (const int*)d_in[5];
    const int*   ui_dst = (const int*)d_in[6];
    const float* ui_val = (const float*)d_in[7];
    const float* emb    = (const float*)d_in[8];
    const float* att    = (const float*)d_in[9];

    const int Eii = in_sizes[2];
    const int Eui = in_sizes[5];
    const int Bp  = in_sizes[0];

    const int TPB = 256;
    int preN = (NB / 8 > Eii) ? NB / 8 : Eii;
    if (Bp * 16 > preN) preN = Bp * 16;
    const int preGrid  = (preN + TPB - 1) / TPB;
    const int scatGrid = (((Eii + 7) >> 3) + TPB - 1) / TPB;
    const int rowGrid  = (M_ITEMS + (TPB / 32) - 1) / (TPB / 32);
    const int filtGrid = (((Eui + 3) >> 2) + TPB - 1) / TPB;

    uint2 *h0, *h1, *h2;
    cudaGetSymbolAddress((void**)&h0, g_h0);
    cudaGetSymbolAddress((void**)&h1, g_h1);
    cudaGetSymbolAddress((void**)&h2, g_h2);

    // 0: fused init (h0) + histogram + user flag/zero + counter resets
    k_pre<<<preGrid, TPB>>>(emb, ii_src, Eii, users, Bp);
    // 1: single-kernel lookback scan (writes rowptr/pos, zeroes cnt)
    k_scan<<<SCAN_BLOCKS, 256>>>();
    // 2: scatter into CSR, 8 edges/thread, dst premultiplied
    k_scatter<<<scatGrid, TPB>>>(ii_src, ii_dst, ii_val, Eii);

    // 3-5: pull-based LightGCN layers (idx 3 = profiled launch).
    // Layer 2 fuses the fp32 sum build (k_post) into its epilogue.
    k_spmm_pull<<<rowGrid, TPB>>>(h0, h1,      att, 0, nullptr);  // half(emb) -> e1
    k_spmm_pull<<<rowGrid, TPB>>>(h1, h2,      att, 1, nullptr);  // e1 -> e2
    k_spmm_pull<<<rowGrid, TPB>>>(h2, nullptr, att, 2, emb);      // e2 -> g_sum

    // 6: compact batch-user edges (4/thread);  7: process compacted list
    k_ui_filter<<<filtGrid, TPB>>>(ui_src, ui_dst, ui_val, Eui);
    k_ui_gather<<<1184, TPB>>>();
    // 8: final per-pair dots
    k_dot<<<(Bp * 32 + TPB - 1) / TPB, TPB>>>(users, items, (float*)d_out, Bp);
}

// round 16
// speedup vs baseline: 1.0428x; 1.0428x over previous
#include <cuda_runtime.h>
#include <cuda_fp16.h>
#include <cstdint>

// Problem constants (fixed by the reference)
#define M_ITEMS 100000
#define N_USERS 50000
#define DIM     64
#define NB      (M_ITEMS * DIM)   // 6,400,000 floats
#define NU      (N_USERS * DIM)   // 3,200,000 floats
#define E_II_MAX 3200000
#define E_UI_MAX 1600000

#define SCAN_CHUNK  1024
#define SCAN_BLOCKS ((M_ITEMS + SCAN_CHUNK - 1) / SCAN_CHUNK)  // 98

// Static device scratch (no allocations allowed).
__device__ uint2 g_h0[NB / 4];          // half(emb) -> later e3
__device__ uint2 g_h1[NB / 4];          // e1
__device__ uint2 g_h2[NB / 4];          // e2
__device__ float g_sum[NB];             // all_items*4 (built once by k_post)
__device__ float g_users[NU];           // all_users (only batch rows zeroed/used)
__device__ int   g_cnt[M_ITEMS];        // per-row counts (re-zeroed by k_scan)
__device__ int   g_rowptr[M_ITEMS + 1]; // CSR row pointers
__device__ int   g_pos[M_ITEMS];        // scatter fill cursors
__device__ int2  g_epack[E_II_MAX];     // CSR: (dst*16, val-bits) per edge
__device__ int   g_sync[SCAN_BLOCKS];   // lookback: aggregate+1, 0 = not ready
__device__ unsigned char g_uflag[N_USERS]; // batch-user flags (set-only, idempotent)
__device__ int   g_uecnt;               // compacted ui-edge count (reset in k_pre)
__device__ int4  g_ue4[E_UI_MAX];       // compacted ui edges: (u*16, i*16, valbits, -)

// Vector reduction-add to global (sm_90+)
__device__ __forceinline__ void red_add_f4(float4* addr, float4 v) {
    asm volatile("red.global.add.v4.f32 [%0], {%1, %2, %3, %4};"
                 :: "l"(addr), "f"(v.x), "f"(v.y), "f"(v.z), "f"(v.w)
                 : "memory");
}

// Streaming (evict-first) accesses for once-touched data.
__device__ __forceinline__ int2 ldcs_int2(const int2* p) {
    int2 r;
    asm volatile("ld.global.cs.v2.b32 {%0, %1}, [%2];"
                 : "=r"(r.x), "=r"(r.y) : "l"(p));
    return r;
}
__device__ __forceinline__ void stcs_uint2(uint2* p, uint2 v) {
    asm volatile("st.global.cs.v2.b32 [%0], {%1, %2};"
                 :: "l"(p), "r"(v.x), "r"(v.y));
}

__device__ __forceinline__ int block_reduce_sum(int v, int* sw) {
    #pragma unroll
    for (int o = 16; o; o >>= 1) v += __shfl_xor_sync(0xFFFFFFFFu, v, o);
    int w = threadIdx.x >> 5;
    if ((threadIdx.x & 31) == 0) sw[w] = v;
    __syncthreads();
    if (threadIdx.x < 8) {
        v = sw[threadIdx.x];
        #pragma unroll
        for (int o = 4; o; o >>= 1) v += __shfl_xor_sync(0xFFu, v, o);
        if (threadIdx.x == 0) sw[0] = v;
    }
    __syncthreads();
    int r = sw[0];
    __syncthreads();
    return r;
}

// Fused: g_h0 = half(emb), histogram of ii_src, batch-user flag + row zeroing,
// counter resets.
__global__ void k_pre(const float* __restrict__ emb, const int* __restrict__ src,
                      int ne, const int* __restrict__ users, int nusers) {
    int i = blockIdx.x * blockDim.x + threadIdx.x;
    if (i < NB / 8) {
        const float4* e4 = (const float4*)emb;
        float4 a = __ldg(e4 + 2 * i);
        float4 b = __ldg(e4 + 2 * i + 1);
        __half2 h0 = __floats2half2_rn(a.x, a.y);
        __half2 h1 = __floats2half2_rn(a.z, a.w);
        __half2 h2 = __floats2half2_rn(b.x, b.y);
        __half2 h3 = __floats2half2_rn(b.z, b.w);
        uint4 hp;
        hp.x = *reinterpret_cast<unsigned int*>(&h0);
        hp.y = *reinterpret_cast<unsigned int*>(&h1);
        hp.z = *reinterpret_cast<unsigned int*>(&h2);
        hp.w = *reinterpret_cast<unsigned int*>(&h3);
        ((uint4*)g_h0)[i] = hp;
    }
    if (i < nusers * 16) {
        int b = i >> 4, l = i & 15;
        int u = __ldg(users + b);
        if (l == 0) g_uflag[u] = 1;
        ((float4*)g_users)[(long)u * 16 + l] = make_float4(0.f, 0.f, 0.f, 0.f);
    }
    if (i < SCAN_BLOCKS) g_sync[i] = 0;
    if (i == 0) g_uecnt = 0;
    if (i < ne) atomicAdd(&g_cnt[__ldg(src + i)], 1);
}

// Single-kernel exclusive scan with decoupled lookback (98 co-resident blocks).
__global__ void k_scan() {
    __shared__ int s[256];
    __shared__ int sw[8];
    int tid = threadIdx.x, b = blockIdx.x;

    int idx0 = b * SCAN_CHUNK + tid * 4;
    int c[4];
    #pragma unroll
    for (int i = 0; i < 4; i++) {
        int idx = idx0 + i;
        c[i] = (idx < M_ITEMS) ? g_cnt[idx] : 0;
    }
    int t4 = c[0] + c[1] + c[2] + c[3];

    int agg = block_reduce_sum(t4, sw);
    if (tid == 0) atomicExch(&g_sync[b], agg + 1);

    int pre = 0;
    if (tid < b) {
        int v;
        do { v = atomicAdd(&g_sync[tid], 0); } while (v == 0);
        pre = v - 1;
    }
    int blockOff = block_reduce_sum(pre, sw);

    s[tid] = t4;
    __syncthreads();
    for (int off = 1; off < 256; off <<= 1) {
        int t = (tid >= off) ? s[tid - off] : 0;
        __syncthreads();
        s[tid] += t;
        __syncthreads();
    }
    int run = blockOff + ((tid == 0) ? 0 : s[tid - 1]);
    #pragma unroll
    for (int i = 0; i < 4; i++) {
        int idx = idx0 + i;
        if (idx < M_ITEMS) {
            g_rowptr[idx] = run;
            g_pos[idx]    = run;
            g_cnt[idx]    = 0;
            run += c[i];
        }
    }
    if (b == SCAN_BLOCKS - 1 && tid == 255) g_rowptr[M_ITEMS] = run;
}

// Dual-role kernel: blocks [0, scatBlocks) scatter ii edges into CSR order
// (8 independent edges per thread, dst premultiplied by 16); the remaining
// blocks compact batch-user ui edges (4 edges/thread). Both roles are
// latency-bound scatter chains with no mutual dependency — co-residency
// overlaps their memory latencies instead of serializing two
// under-utilized kernels.
__global__ void k_scatter_filter(const int* __restrict__ src, const int* __restrict__ dst,
                                 const float* __restrict__ val, int n,
                                 const int* __restrict__ usrc, const int* __restrict__ udst,
                                 const float* __restrict__ uval, int nu,
                                 int scatBlocks) {
    if (blockIdx.x < (unsigned)scatBlocks) {
        // ---- ii-CSR scatter ----
        int i = blockIdx.x * blockDim.x + threadIdx.x;
        int Q = (n + 7) >> 3;
        if (i >= Q) return;
        int e[8]; int s[8]; int2 dv[8]; int p[8];
        #pragma unroll
        for (int k = 0; k < 8; k++) {
            e[k] = i + k * Q;
            if (e[k] < n) {
                s[k]  = __ldg(src + e[k]);
                dv[k] = make_int2(__ldg(dst + e[k]) << 4, __float_as_int(__ldg(val + e[k])));
            }
        }
        #pragma unroll
        for (int k = 0; k < 8; k++)
            if (e[k] < n) p[k] = atomicAdd(&g_pos[s[k]], 1);
        #pragma unroll
        for (int k = 0; k < 8; k++)
            if (e[k] < n) g_epack[p[k]] = dv[k];
    } else {
        // ---- ui batch-user edge compaction ----
        int i = (blockIdx.x - scatBlocks) * blockDim.x + threadIdx.x;
        int Q = (nu + 3) >> 2;
        if (i >= Q) return;
        int e[4]; int s[4]; unsigned char f[4];
        #pragma unroll
        for (int k = 0; k < 4; k++) {
            e[k] = i + k * Q;
            s[k] = (e[k] < nu) ? __ldg(usrc + e[k]) : 0;
        }
        #pragma unroll
        for (int k = 0; k < 4; k++)
            f[k] = (e[k] < nu) ? g_uflag[s[k]] : 0;
        #pragma unroll
        for (int k = 0; k < 4; k++) {
            if (f[k]) {
                int p = atomicAdd(&g_uecnt, 1);
                g_ue4[p] = make_int4(s[k] << 4, __ldg(udst + e[k]) << 4,
                                     __float_as_int(__ldg(uval + e[k])), 0);
            }
        }
    }
}

// Pull SpMM (proven shape): one warp per row, TWO edges per iteration
// (16 lanes/edge), 8B/lane. Edge records .cs, gathers .nc, output .cs half.
__global__ void k_spmm_pull(const uint2* __restrict__ x, uint2* __restrict__ yh,
                            const float* __restrict__ att, int layer) {
    int row  = blockIdx.x * (blockDim.x >> 5) + (threadIdx.x >> 5);
    int lane = threadIdx.x & 31;
    if (row >= M_ITEMS) return;
    int lane16 = lane & 15;
    int sub    = lane >> 4;

    int beg = g_rowptr[row];
    int end = g_rowptr[row + 1];

    float4 acc = make_float4(0.0f, 0.0f, 0.0f, 0.0f);

    if ((end - beg) & 1) {                    // peel odd edge
        int2 ed = ldcs_int2(&g_epack[beg]);
        float v = (sub == 0) ? __int_as_float(ed.y) : 0.0f;
        uint2 raw = __ldg(x + (unsigned)(ed.x | lane16));
        float2 f0 = __half22float2(*reinterpret_cast<__half2*>(&raw.x));
        float2 f1 = __half22float2(*reinterpret_cast<__half2*>(&raw.y));
        acc.x = fmaf(v, f0.x, acc.x);
        acc.y = fmaf(v, f0.y, acc.y);
        acc.z = fmaf(v, f1.x, acc.z);
        acc.w = fmaf(v, f1.y, acc.w);
        beg++;
    }
    #pragma unroll 4
    for (int e = beg; e < end; e += 2) {
        int2  ed = ldcs_int2(&g_epack[e + sub]);
        float v  = __int_as_float(ed.y);
        uint2 raw = __ldg(x + (unsigned)(ed.x | lane16));
        float2 f0 = __half22float2(*reinterpret_cast<__half2*>(&raw.x));
        float2 f1 = __half22float2(*reinterpret_cast<__half2*>(&raw.y));
        acc.x = fmaf(v, f0.x, acc.x);
        acc.y = fmaf(v, f0.y, acc.y);
        acc.z = fmaf(v, f1.x, acc.z);
        acc.w = fmaf(v, f1.y, acc.w);
    }
    acc.x += __shfl_xor_sync(0xFFFFFFFFu, acc.x, 16);
    acc.y += __shfl_xor_sync(0xFFFFFFFFu, acc.y, 16);
    acc.z += __shfl_xor_sync(0xFFFFFFFFu, acc.z, 16);
    acc.w += __shfl_xor_sync(0xFFFFFFFFu, acc.w, 16);

    if (sub == 0) {
        float a = __ldg(att + layer);
        __half2 p0 = __floats2half2_rn(acc.x * a, acc.y * a);
        __half2 p1 = __floats2half2_rn(acc.z * a, acc.w * a);
        uint2 hp;
        hp.x = *reinterpret_cast<unsigned int*>(&p0);
        hp.y = *reinterpret_cast<unsigned int*>(&p1);
        stcs_uint2(yh + ((unsigned)row * 16u + lane16), hp);
    }
}

// Build g_sum = emb + e1 + e2 + e3 (fp32, halves widened), vectorized.
__global__ void k_post(const float* __restrict__ emb) {
    int i = blockIdx.x * blockDim.x + threadIdx.x;
    if (i >= NB / 8) return;
    const float4* e4 = (const float4*)emb;
    float4 a = __ldg(e4 + 2 * i);
    float4 b = __ldg(e4 + 2 * i + 1);
    uint4 x1 = ((const uint4*)g_h1)[i];
    uint4 x2 = ((const uint4*)g_h2)[i];
    uint4 x3 = ((const uint4*)g_h0)[i];   // e3 overwrote half(emb)
    #pragma unroll
    for (int q = 0; q < 3; q++) {
        uint4 u = (q == 0) ? x1 : (q == 1) ? x2 : x3;
        float2 f0 = __half22float2(*reinterpret_cast<__half2*>(&u.x));
        float2 f1 = __half22float2(*reinterpret_cast<__half2*>(&u.y));
        float2 f2 = __half22float2(*reinterpret_cast<__half2*>(&u.z));
        float2 f3 = __half22float2(*reinterpret_cast<__half2*>(&u.w));
        a.x += f0.x; a.y += f0.y; a.z += f1.x; a.w += f1.y;
        b.x += f2.x; b.y += f2.y; b.z += f3.x; b.w += f3.y;
    }
    ((float4*)g_sum)[2 * i]     = a;
    ((float4*)g_sum)[2 * i + 1] = b;
}

// ui phase B: grid-stride over the compacted list, 2 edges/warp, 16 lanes/edge.
__global__ void k_ui_gather() {
    int K = g_uecnt;
    int warps = (gridDim.x * blockDim.x) >> 5;
    int w     = (blockIdx.x * blockDim.x + threadIdx.x) >> 5;
    int lane  = threadIdx.x & 31;
    int lane16 = lane & 15;
    int sub    = lane >> 4;

    for (int i = w * 2 + sub; i < K; i += warps * 2) {
        int4 t = __ldg(&g_ue4[i]);
        float v = __int_as_float(t.z) * 0.25f;
        float4 xv = __ldg((const float4*)g_sum + (unsigned)(t.y | lane16));
        float4 r  = make_float4(xv.x * v, xv.y * v, xv.z * v, xv.w * v);
        red_add_f4((float4*)g_users + (unsigned)(t.x | lane16), r);
    }
}

// gamma[b] = dot(g_users[u], 0.25 * g_sum[i]); one warp per pair
__global__ void k_dot(const int* __restrict__ users, const int* __restrict__ items,
                      float* __restrict__ out, int nb) {
    int w    = (blockIdx.x * blockDim.x + threadIdx.x) >> 5;
    int lane = threadIdx.x & 31;
    if (w >= nb) return;

    int u = __ldg(users + w);
    int i = __ldg(items + w);

    float2 a = __ldg((const float2*)g_users + (long)u * 32 + lane);
    float2 b = __ldg((const float2*)g_sum   + (long)i * 32 + lane);
    float p = a.x * b.x + a.y * b.y;

    #pragma unroll
    for (int o = 16; o; o >>= 1) p += __shfl_xor_sync(0xFFFFFFFFu, p, o);

    if (lane == 0) out[w] = 0.25f * p;
}

extern "C" void kernel_launch(void* const* d_in, const int* in_sizes, int n_in,
                              void* d_out, int out_size) {
    const int*   users  = (const int*)d_in[0];
    const int*   items  = (const int*)d_in[1];
    const int*   ii_src = (const int*)d_in[2];
    const int*   ii_dst = (const int*)d_in[3];
    const float* ii_val = (const float*)d_in[4];
    const int*   ui_src = (const int*)d_in[5];
    const int*   ui_dst = (const int*)d_in[6];
    const float* ui_val = (const float*)d_in[7];
    const float* emb    = (const float*)d_in[8];
    const float* att    = (const float*)d_in[9];

    const int Eii = in_sizes[2];
    const int Eui = in_sizes[5];
    const int Bp  = in_sizes[0];

    const int TPB = 256;
    int preN = (NB / 8 > Eii) ? NB / 8 : Eii;
    if (Bp * 16 > preN) preN = Bp * 16;
    const int preGrid  = (preN + TPB - 1) / TPB;
    const int scatGrid = (((Eii + 7) >> 3) + TPB - 1) / TPB;
    const int filtGrid = (((Eui + 3) >> 2) + TPB - 1) / TPB;
    const int rowGrid  = (M_ITEMS + (TPB / 32) - 1) / (TPB / 32);
    const int nb8Grid  = (NB / 8 + TPB - 1) / TPB;

    uint2 *h0, *h1, *h2;
    cudaGetSymbolAddress((void**)&h0, g_h0);
    cudaGetSymbolAddress((void**)&h1, g_h1);
    cudaGetSymbolAddress((void**)&h2, g_h2);

    // 0: fused init (h0) + histogram + user flag/zero + counter resets
    k_pre<<<preGrid, TPB>>>(emb, ii_src, Eii, users, Bp);
    // 1: single-kernel lookback scan (writes rowptr/pos, zeroes cnt)
    k_scan<<<SCAN_BLOCKS, 256>>>();
    // 2: fused ii-CSR scatter + ui edge compaction (independent roles overlap)
    k_scatter_filter<<<scatGrid + filtGrid, TPB>>>(ii_src, ii_dst, ii_val, Eii,
                                                   ui_src, ui_dst, ui_val, Eui,
                                                   scatGrid);

    // 3-5: pull-based LightGCN layers (idx 3 = profiled launch)
    k_spmm_pull<<<rowGrid, TPB>>>(h0, h1, att, 0);  // half(emb) -> e1
    k_spmm_pull<<<rowGrid, TPB>>>(h1, h2, att, 1);  // e1 -> e2
    k_spmm_pull<<<rowGrid, TPB>>>(h2, h0, att, 2);  // e2 -> e3 (reuse h0)

    // 6: fold layers into fp32 sum (= 4 * all_items)
    k_post<<<nb8Grid, TPB>>>(emb);

    // 7: process compacted ui list
    k_ui_gather<<<1184, TPB>>>();
    // 8: final per-pair dots
    k_dot<<<(Bp * 32 + TPB - 1) / TPB, TPB>>>(users, items, (float*)d_out, Bp);
}

// round 17
// speedup vs baseline: 1.0456x; 1.0026x over previous
#include <cuda_runtime.h>
#include <cuda_fp16.h>
#include <cstdint>

// Problem constants (fixed by the reference)
#define M_ITEMS 100000
#define N_USERS 50000
#define DIM     64
#define NB      (M_ITEMS * DIM)   // 6,400,000 floats
#define NU      (N_USERS * DIM)   // 3,200,000 floats
#define E_II_MAX 3200000
#define E_UI_MAX 1600000

#define SCAN_CHUNK  1024
#define SCAN_BLOCKS ((M_ITEMS + SCAN_CHUNK - 1) / SCAN_CHUNK)  // 98

// Static device scratch (no allocations allowed).
__device__ uint2 g_h0[NB / 4];          // half(emb) -> later e3
__device__ uint2 g_h1[NB / 4];          // e1
__device__ uint2 g_h2[NB / 4];          // e2
__device__ float g_sum[NB];             // all_items*4 (built once by k_post)
__device__ float g_users[NU];           // all_users (only batch rows zeroed/used)
__device__ int   g_cnt[M_ITEMS];        // per-row counts (re-zeroed by k_scan)
__device__ int   g_rowptr[M_ITEMS + 1]; // CSR row pointers
__device__ int   g_pos[M_ITEMS];        // scatter fill cursors
__device__ int2  g_epack[E_II_MAX];     // CSR: (dst*16, val-bits) per edge
__device__ int   g_sync[SCAN_BLOCKS];   // lookback: aggregate+1, 0 = not ready
__device__ unsigned char g_uflag[N_USERS]; // batch-user flags (set-only, idempotent)
__device__ int   g_uecnt;               // compacted ui-edge count (reset in k_pre)
__device__ int4  g_ue4[E_UI_MAX];       // compacted ui edges: (u*16, i*16, valbits, -)

// Vector reduction-add to global (sm_90+)
__device__ __forceinline__ void red_add_f4(float4* addr, float4 v) {
    asm volatile("red.global.add.v4.f32 [%0], {%1, %2, %3, %4};"
                 :: "l"(addr), "f"(v.x), "f"(v.y), "f"(v.z), "f"(v.w)
                 : "memory");
}

// Streaming (evict-first) accesses for once-touched data.
__device__ __forceinline__ int2 ldcs_int2(const int2* p) {
    int2 r;
    asm volatile("ld.global.cs.v2.b32 {%0, %1}, [%2];"
                 : "=r"(r.x), "=r"(r.y) : "l"(p));
    return r;
}
__device__ __forceinline__ void stcs_uint2(uint2* p, uint2 v) {
    asm volatile("st.global.cs.v2.b32 [%0], {%1, %2};"
                 :: "l"(p), "r"(v.x), "r"(v.y));
}

__device__ __forceinline__ int block_reduce_sum(int v, int* sw) {
    #pragma unroll
    for (int o = 16; o; o >>= 1) v += __shfl_xor_sync(0xFFFFFFFFu, v, o);
    int w = threadIdx.x >> 5;
    if ((threadIdx.x & 31) == 0) sw[w] = v;
    __syncthreads();
    if (threadIdx.x < 8) {
        v = sw[threadIdx.x];
        #pragma unroll
        for (int o = 4; o; o >>= 1) v += __shfl_xor_sync(0xFFu, v, o);
        if (threadIdx.x == 0) sw[0] = v;
    }
    __syncthreads();
    int r = sw[0];
    __syncthreads();
    return r;
}

// Fused: g_h0 = half(emb), histogram of ii_src (4 edges/thread, MLP=4),
// batch-user flag + row zeroing, counter resets.
__global__ void k_pre(const float* __restrict__ emb, const int* __restrict__ src,
                      int ne, const int* __restrict__ users, int nusers) {
    int i = blockIdx.x * blockDim.x + threadIdx.x;
    if (i < NB / 8) {
        const float4* e4 = (const float4*)emb;
        float4 a = __ldg(e4 + 2 * i);
        float4 b = __ldg(e4 + 2 * i + 1);
        __half2 h0 = __floats2half2_rn(a.x, a.y);
        __half2 h1 = __floats2half2_rn(a.z, a.w);
        __half2 h2 = __floats2half2_rn(b.x, b.y);
        __half2 h3 = __floats2half2_rn(b.z, b.w);
        uint4 hp;
        hp.x = *reinterpret_cast<unsigned int*>(&h0);
        hp.y = *reinterpret_cast<unsigned int*>(&h1);
        hp.z = *reinterpret_cast<unsigned int*>(&h2);
        hp.w = *reinterpret_cast<unsigned int*>(&h3);
        ((uint4*)g_h0)[i] = hp;
    }
    if (i < nusers * 16) {
        int b = i >> 4, l = i & 15;
        int u = __ldg(users + b);
        if (l == 0) g_uflag[u] = 1;
        ((float4*)g_users)[(long)u * 16 + l] = make_float4(0.f, 0.f, 0.f, 0.f);
    }
    if (i < SCAN_BLOCKS) g_sync[i] = 0;
    if (i == 0) g_uecnt = 0;
    // histogram: 4 independent edges per thread (MLP=4 on the atomic chains)
    {
        int Q = (ne + 3) >> 2;
        if (i < Q) {
            int s[4]; int e[4];
            #pragma unroll
            for (int k = 0; k < 4; k++) {
                e[k] = i + k * Q;
                s[k] = (e[k] < ne) ? __ldg(src + e[k]) : 0;
            }
            #pragma unroll
            for (int k = 0; k < 4; k++)
                if (e[k] < ne) atomicAdd(&g_cnt[s[k]], 1);
        }
    }
}

// Single-kernel exclusive scan with decoupled lookback (98 co-resident blocks).
__global__ void k_scan() {
    __shared__ int s[256];
    __shared__ int sw[8];
    int tid = threadIdx.x, b = blockIdx.x;

    int idx0 = b * SCAN_CHUNK + tid * 4;
    int c[4];
    #pragma unroll
    for (int i = 0; i < 4; i++) {
        int idx = idx0 + i;
        c[i] = (idx < M_ITEMS) ? g_cnt[idx] : 0;
    }
    int t4 = c[0] + c[1] + c[2] + c[3];

    int agg = block_reduce_sum(t4, sw);
    if (tid == 0) atomicExch(&g_sync[b], agg + 1);

    int pre = 0;
    if (tid < b) {
        int v;
        do { v = atomicAdd(&g_sync[tid], 0); } while (v == 0);
        pre = v - 1;
    }
    int blockOff = block_reduce_sum(pre, sw);

    s[tid] = t4;
    __syncthreads();
    for (int off = 1; off < 256; off <<= 1) {
        int t = (tid >= off) ? s[tid - off] : 0;
        __syncthreads();
        s[tid] += t;
        __syncthreads();
    }
    int run = blockOff + ((tid == 0) ? 0 : s[tid - 1]);
    #pragma unroll
    for (int i = 0; i < 4; i++) {
        int idx = idx0 + i;
        if (idx < M_ITEMS) {
            g_rowptr[idx] = run;
            g_pos[idx]    = run;
            g_cnt[idx]    = 0;
            run += c[i];
        }
    }
    if (b == SCAN_BLOCKS - 1 && tid == 255) g_rowptr[M_ITEMS] = run;
}

// Dual-role kernel: blocks [0, scatBlocks) scatter ii edges into CSR order
// (8 independent edges per thread, dst premultiplied by 16); the remaining
// blocks compact batch-user ui edges (4 edges/thread). Both roles are
// latency-bound scatter chains with no mutual dependency — co-residency
// overlaps their memory latencies.
__global__ void k_scatter_filter(const int* __restrict__ src, const int* __restrict__ dst,
                                 const float* __restrict__ val, int n,
                                 const int* __restrict__ usrc, const int* __restrict__ udst,
                                 const float* __restrict__ uval, int nu,
                                 int scatBlocks) {
    if (blockIdx.x < (unsigned)scatBlocks) {
        // ---- ii-CSR scatter ----
        int i = blockIdx.x * blockDim.x + threadIdx.x;
        int Q = (n + 7) >> 3;
        if (i >= Q) return;
        int e[8]; int s[8]; int2 dv[8]; int p[8];
        #pragma unroll
        for (int k = 0; k < 8; k++) {
            e[k] = i + k * Q;
            if (e[k] < n) {
                s[k]  = __ldg(src + e[k]);
                dv[k] = make_int2(__ldg(dst + e[k]) << 4, __float_as_int(__ldg(val + e[k])));
            }
        }
        #pragma unroll
        for (int k = 0; k < 8; k++)
            if (e[k] < n) p[k] = atomicAdd(&g_pos[s[k]], 1);
        #pragma unroll
        for (int k = 0; k < 8; k++)
            if (e[k] < n) g_epack[p[k]] = dv[k];
    } else {
        // ---- ui batch-user edge compaction ----
        int i = (blockIdx.x - scatBlocks) * blockDim.x + threadIdx.x;
        int Q = (nu + 3) >> 2;
        if (i >= Q) return;
        int e[4]; int s[4]; unsigned char f[4];
        #pragma unroll
        for (int k = 0; k < 4; k++) {
            e[k] = i + k * Q;
            s[k] = (e[k] < nu) ? __ldg(usrc + e[k]) : 0;
        }
        #pragma unroll
        for (int k = 0; k < 4; k++)
            f[k] = (e[k] < nu) ? g_uflag[s[k]] : 0;
        #pragma unroll
        for (int k = 0; k < 4; k++) {
            if (f[k]) {
                int p = atomicAdd(&g_uecnt, 1);
                g_ue4[p] = make_int4(s[k] << 4, __ldg(udst + e[k]) << 4,
                                     __float_as_int(__ldg(uval + e[k])), 0);
            }
        }
    }
}

// Pull SpMM (proven shape): one warp per row, TWO edges per iteration
// (16 lanes/edge), 8B/lane. Edge records .cs, gathers .nc, output .cs half.
__global__ void k_spmm_pull(const uint2* __restrict__ x, uint2* __restrict__ yh,
                            const float* __restrict__ att, int layer) {
    int row  = blockIdx.x * (blockDim.x >> 5) + (threadIdx.x >> 5);
    int lane = threadIdx.x & 31;
    if (row >= M_ITEMS) return;
    int lane16 = lane & 15;
    int sub    = lane >> 4;

    int beg = g_rowptr[row];
    int end = g_rowptr[row + 1];

    float4 acc = make_float4(0.0f, 0.0f, 0.0f, 0.0f);

    if ((end - beg) & 1) {                    // peel odd edge
        int2 ed = ldcs_int2(&g_epack[beg]);
        float v = (sub == 0) ? __int_as_float(ed.y) : 0.0f;
        uint2 raw = __ldg(x + (unsigned)(ed.x | lane16));
        float2 f0 = __half22float2(*reinterpret_cast<__half2*>(&raw.x));
        float2 f1 = __half22float2(*reinterpret_cast<__half2*>(&raw.y));
        acc.x = fmaf(v, f0.x, acc.x);
        acc.y = fmaf(v, f0.y, acc.y);
        acc.z = fmaf(v, f1.x, acc.z);
        acc.w = fmaf(v, f1.y, acc.w);
        beg++;
    }
    #pragma unroll 4
    for (int e = beg; e < end; e += 2) {
        int2  ed = ldcs_int2(&g_epack[e + sub]);
        float v  = __int_as_float(ed.y);
        uint2 raw = __ldg(x + (unsigned)(ed.x | lane16));
        float2 f0 = __half22float2(*reinterpret_cast<__half2*>(&raw.x));
        float2 f1 = __half22float2(*reinterpret_cast<__half2*>(&raw.y));
        acc.x = fmaf(v, f0.x, acc.x);
        acc.y = fmaf(v, f0.y, acc.y);
        acc.z = fmaf(v, f1.x, acc.z);
        acc.w = fmaf(v, f1.y, acc.w);
    }
    acc.x += __shfl_xor_sync(0xFFFFFFFFu, acc.x, 16);
    acc.y += __shfl_xor_sync(0xFFFFFFFFu, acc.y, 16);
    acc.z += __shfl_xor_sync(0xFFFFFFFFu, acc.z, 16);
    acc.w += __shfl_xor_sync(0xFFFFFFFFu, acc.w, 16);

    if (sub == 0) {
        float a = __ldg(att + layer);
        __half2 p0 = __floats2half2_rn(acc.x * a, acc.y * a);
        __half2 p1 = __floats2half2_rn(acc.z * a, acc.w * a);
        uint2 hp;
        hp.x = *reinterpret_cast<unsigned int*>(&p0);
        hp.y = *reinterpret_cast<unsigned int*>(&p1);
        stcs_uint2(yh + ((unsigned)row * 16u + lane16), hp);
    }
}

// Build g_sum = emb + e1 + e2 + e3 (fp32, halves widened), vectorized.
__global__ void k_post(const float* __restrict__ emb) {
    int i = blockIdx.x * blockDim.x + threadIdx.x;
    if (i >= NB / 8) return;
    const float4* e4 = (const float4*)emb;
    float4 a = __ldg(e4 + 2 * i);
    float4 b = __ldg(e4 + 2 * i + 1);
    uint4 x1 = ((const uint4*)g_h1)[i];
    uint4 x2 = ((const uint4*)g_h2)[i];
    uint4 x3 = ((const uint4*)g_h0)[i];   // e3 overwrote half(emb)
    #pragma unroll
    for (int q = 0; q < 3; q++) {
        uint4 u = (q == 0) ? x1 : (q == 1) ? x2 : x3;
        float2 f0 = __half22float2(*reinterpret_cast<__half2*>(&u.x));
        float2 f1 = __half22float2(*reinterpret_cast<__half2*>(&u.y));
        float2 f2 = __half22float2(*reinterpret_cast<__half2*>(&u.z));
        float2 f3 = __half22float2(*reinterpret_cast<__half2*>(&u.w));
        a.x += f0.x; a.y += f0.y; a.z += f1.x; a.w += f1.y;
        b.x += f2.x; b.y += f2.y; b.z += f3.x; b.w += f3.y;
    }
    ((float4*)g_sum)[2 * i]     = a;
    ((float4*)g_sum)[2 * i + 1] = b;
}

// ui phase B: grid-stride over the compacted list, 2 edges/warp per stream,
// TWO independent streams in flight per warp (MLP=2 on record->gather chains).
__global__ void k_ui_gather() {
    int K = g_uecnt;
    int warps  = (gridDim.x * blockDim.x) >> 5;
    int w      = (blockIdx.x * blockDim.x + threadIdx.x) >> 5;
    int lane   = threadIdx.x & 31;
    int lane16 = lane & 15;
    int sub    = lane >> 4;
    int stride = warps * 2;

    for (int i = w * 2 + sub; i < K; i += stride * 2) {
        int j = i + stride;
        int4 t0 = __ldg(&g_ue4[i]);
        int4 t1 = (j < K) ? __ldg(&g_ue4[j]) : make_int4(0, 0, 0, 0);

        float v0 = __int_as_float(t0.z) * 0.25f;
        float4 x0 = __ldg((const float4*)g_sum + (unsigned)(t0.y | lane16));
        float4 r0 = make_float4(x0.x * v0, x0.y * v0, x0.z * v0, x0.w * v0);
        red_add_f4((float4*)g_users + (unsigned)(t0.x | lane16), r0);

        if (j < K) {
            float v1 = __int_as_float(t1.z) * 0.25f;
            float4 x1 = __ldg((const float4*)g_sum + (unsigned)(t1.y | lane16));
            float4 r1 = make_float4(x1.x * v1, x1.y * v1, x1.z * v1, x1.w * v1);
            red_add_f4((float4*)g_users + (unsigned)(t1.x | lane16), r1);
        }
    }
}

// gamma[b] = dot(g_users[u], 0.25 * g_sum[i]); one warp per pair
__global__ void k_dot(const int* __restrict__ users, const int* __restrict__ items,
                      float* __restrict__ out, int nb) {
    int w    = (blockIdx.x * blockDim.x + threadIdx.x) >> 5;
    int lane = threadIdx.x & 31;
    if (w >= nb) return;

    int u = __ldg(users + w);
    int i = __ldg(items + w);

    float2 a = __ldg((const float2*)g_users + (long)u * 32 + lane);
    float2 b = __ldg((const float2*)g_sum   + (long)i * 32 + lane);
    float p = a.x * b.x + a.y * b.y;

    #pragma unroll
    for (int o = 16; o; o >>= 1) p += __shfl_xor_sync(0xFFFFFFFFu, p, o);

    if (lane == 0) out[w] = 0.25f * p;
}

extern "C" void kernel_launch(void* const* d_in, const int* in_sizes, int n_in,
                              void* d_out, int out_size) {
    const int*   users  = (const int*)d_in[0];
    const int*   items  = (const int*)d_in[1];
    const int*   ii_src = (const int*)d_in[2];
    const int*   ii_dst = (const int*)d_in[3];
    const float* ii_val = (const float*)d_in[4];
    const int*   ui_src = (const int*)d_in[5];
    const int*   ui_dst = (const int*)d_in[6];
    const float* ui_val = (const float*)d_in[7];
    const float* emb    = (const float*)d_in[8];
    const float* att    = (const float*)d_in[9];

    const int Eii = in_sizes[2];
    const int Eui = in_sizes[5];
    const int Bp  = in_sizes[0];

    const int TPB = 256;
    int preN = NB / 8;                              // 800K: conversion work
    int histQ = (Eii + 3) >> 2;                     // 800K: 4-edge hist threads
    if (histQ > preN) preN = histQ;
    if (Bp * 16 > preN) preN = Bp * 16;
    const int preGrid  = (preN + TPB - 1) / TPB;
    const int scatGrid = (((Eii + 7) >> 3) + TPB - 1) / TPB;
    const int filtGrid = (((Eui + 3) >> 2) + TPB - 1) / TPB;
    const int rowGrid  = (M_ITEMS + (TPB / 32) - 1) / (TPB / 32);
    const int nb8Grid  = (NB / 8 + TPB - 1) / TPB;

    uint2 *h0, *h1, *h2;
    cudaGetSymbolAddress((void**)&h0, g_h0);
    cudaGetSymbolAddress((void**)&h1, g_h1);
    cudaGetSymbolAddress((void**)&h2, g_h2);

    // 0: fused init (h0) + 4-edge histogram + user flag/zero + counter resets
    k_pre<<<preGrid, TPB>>>(emb, ii_src, Eii, users, Bp);
    // 1: single-kernel lookback scan (writes rowptr/pos, zeroes cnt)
    k_scan<<<SCAN_BLOCKS, 256>>>();
    // 2: fused ii-CSR scatter + ui edge compaction (independent roles overlap)
    k_scatter_filter<<<scatGrid + filtGrid, TPB>>>(ii_src, ii_dst, ii_val, Eii,
                                                   ui_src, ui_dst, ui_val, Eui,
                                                   scatGrid);

    // 3-5: pull-based LightGCN layers (idx 3 = profiled launch)
    k_spmm_pull<<<rowGrid, TPB>>>(h0, h1, att, 0);  // half(emb) -> e1
    k_spmm_pull<<<rowGrid, TPB>>>(h1, h2, att, 1);  // e1 -> e2
    k_spmm_pull<<<rowGrid, TPB>>>(h2, h0, att, 2);  // e2 -> e3 (reuse h0)

    // 6: fold layers into fp32 sum (= 4 * all_items)
    k_post<<<nb8Grid, TPB>>>(emb);

    // 7: process compacted ui list (2 streams/warp)
    k_ui_gather<<<2368, TPB>>>();
    // 8: final per-pair dots
    k_dot<<<(Bp * 32 + TPB - 1) / TPB, TPB>>>(users, items, (float*)d_out, Bp);
}